// round 3
// baseline (speedup 1.0000x reference)
#include <cuda_runtime.h>
#include <math.h>

// Problem constants
#define NB   128
#define NI   784
#define NH   410
#define NO   10
#define TSAMP 300
#define KLEN 64
#define THETA 10.0f

// Scratch (device globals: no allocation allowed)
__device__ float g_a1[NB * NH * TSAMP];   // fc1 pre-PSP activations (63 MB)
__device__ float g_s1[NB * NH * TSAMP];   // hidden spikes (63 MB)

// ---------------------------------------------------------------------------
// Kernel 1: fused Poisson encoding + fc1 GEMM
//   a1[n,o,t] = sum_i W1[o,i] * (rand_u[n,i,t] < img[n,i])
// Tiles: O=64, T=64, K-chunk=16. 256 threads, 4x4 micro-tile per thread.
// ---------------------------------------------------------------------------
#define OT 64
#define TTILE 64
#define KC 16

__global__ __launch_bounds__(256) void gemm1_kernel(
    const float* __restrict__ img,
    const float* __restrict__ ru,
    const float* __restrict__ W1)
{
    __shared__ float imgs[NI];
    __shared__ float Ws[OT][KC];      // [o][k]
    __shared__ float Ss[KC][TTILE];   // [k][t]

    const int n  = blockIdx.z;
    const int o0 = blockIdx.y * OT;
    const int t0 = blockIdx.x * TTILE;
    const int tid = threadIdx.x;

    // stage img row for this batch
    for (int i = tid; i < NI; i += 256) imgs[i] = img[n * NI + i];
    __syncthreads();

    const int tx = tid & 15;   // t micro position
    const int ty = tid >> 4;   // o micro position

    float acc[4][4];
#pragma unroll
    for (int a = 0; a < 4; a++)
#pragma unroll
        for (int b = 0; b < 4; b++) acc[a][b] = 0.0f;

    const float* run = ru + (size_t)n * NI * TSAMP;

    const int lk  = tid & 15;   // W-load: k index
    const int lo  = tid >> 4;   // W-load: o base
    const int lt  = tid & 63;   // S-load: t index
    const int lks = tid >> 6;   // S-load: k base

    for (int i0 = 0; i0 < NI; i0 += KC) {
        // load W tile [64][16]
#pragma unroll
        for (int r = 0; r < 4; r++) {
            int oo = lo + 16 * r;
            int og = o0 + oo;
            Ws[oo][lk] = (og < NH) ? W1[og * NI + i0 + lk] : 0.0f;
        }
        // load + encode S tile [16][64]
        {
            int tg = t0 + lt;
#pragma unroll
            for (int r = 0; r < 4; r++) {
                int k = lks + 4 * r;
                float v = 0.0f;
                if (tg < TSAMP) {
                    float rv = run[(size_t)(i0 + k) * TSAMP + tg];
                    v = (rv < imgs[i0 + k]) ? 1.0f : 0.0f;
                }
                Ss[k][lt] = v;
            }
        }
        __syncthreads();

#pragma unroll
        for (int k = 0; k < KC; k++) {
            float wv[4], sv[4];
#pragma unroll
            for (int a = 0; a < 4; a++) wv[a] = Ws[ty * 4 + a][k];
#pragma unroll
            for (int b = 0; b < 4; b++) sv[b] = Ss[k][tx * 4 + b];
#pragma unroll
            for (int a = 0; a < 4; a++)
#pragma unroll
                for (int b = 0; b < 4; b++)
                    acc[a][b] += wv[a] * sv[b];
        }
        __syncthreads();
    }

    // write back (t0 + tx*4 is 16B aligned: 300 % 4 == 0)
#pragma unroll
    for (int a = 0; a < 4; a++) {
        int o = o0 + ty * 4 + a;
        if (o >= NH) continue;
        int t = t0 + tx * 4;
        float* dst = &g_a1[((size_t)n * NH + o) * TSAMP + t];
        if (t + 3 < TSAMP) {
            float4 v = make_float4(acc[a][0], acc[a][1], acc[a][2], acc[a][3]);
            *reinterpret_cast<float4*>(dst) = v;
        } else {
#pragma unroll
            for (int b = 0; b < 4; b++)
                if (t + b < TSAMP) dst[b] = acc[a][b];
        }
    }
}

// ---------------------------------------------------------------------------
// Kernel 2: PSP FIR (K=64) + spike threshold on hidden layer.
// One warp per (n,o) row; each lane computes 10 consecutive t outputs with
// register-blocked k-chunks (16 eps regs x 25 source regs -> 160 FFMA).
// ---------------------------------------------------------------------------
__global__ __launch_bounds__(256) void fir1_kernel()
{
    __shared__ float eps_s[KLEN];
    __shared__ float rows[8][TSAMP];

    const int tid = threadIdx.x;
    if (tid < KLEN) {
        float tv = (float)tid;
        eps_s[tid] = (tv / 10.0f) * expf(1.0f - tv / 10.0f);
    }
    const int w    = tid >> 5;
    const int lane = tid & 31;
    const size_t base = ((size_t)blockIdx.x * 8 + w) * TSAMP;

    for (int t = lane; t < TSAMP; t += 32) rows[w][t] = g_a1[base + t];
    __syncthreads();

    if (lane < 30) {
        const int t0 = lane * 10;
        float acc[10];
#pragma unroll
        for (int j = 0; j < 10; j++) acc[j] = 0.0f;

#pragma unroll
        for (int kb = 0; kb < KLEN; kb += 16) {
            float ev[16];
#pragma unroll
            for (int q = 0; q < 16; q++) ev[q] = eps_s[kb + q];
            float rv[25];
#pragma unroll
            for (int r = 0; r < 25; r++) {
                int idx = t0 + 9 - kb - r;
                rv[r] = (idx >= 0) ? rows[w][idx] : 0.0f;
            }
            // acc[j] += eps[kb+q] * x[t0+j-(kb+q)] ; rv[r] = x[t0+9-kb-r]
#pragma unroll
            for (int j = 0; j < 10; j++)
#pragma unroll
                for (int q = 0; q < 16; q++)
                    acc[j] += ev[q] * rv[(9 - j) + q];
        }
#pragma unroll
        for (int j = 0; j < 10; j++)
            g_s1[base + t0 + j] = (acc[j] >= THETA) ? 1.0f : 0.0f;
    }
}

// ---------------------------------------------------------------------------
// Kernel 3: fused fc2 GEMM + PSP FIR + spike threshold.
// One block per batch n. Thread t computes all 10 output channels.
// ---------------------------------------------------------------------------
#define W2PAD 412   // 410 padded to multiple of 4

__global__ __launch_bounds__(320) void fc2_kernel(
    const float* __restrict__ W2,
    float* __restrict__ out)
{
    __shared__ float W2s[NO * W2PAD];
    __shared__ float a2s[NO][TSAMP + 4];
    __shared__ float eps_s[KLEN];

    const int n = blockIdx.x;
    const int tid = threadIdx.x;

    if (tid < KLEN) {
        float tv = (float)tid;
        eps_s[tid] = (tv / 10.0f) * expf(1.0f - tv / 10.0f);
    }
    for (int i = tid; i < NO * NH; i += 320) {
        int o = i / NH, h = i - o * NH;
        W2s[o * W2PAD + h] = W2[i];
    }
    if (tid < NO * 2) {
        int o = tid >> 1;
        W2s[o * W2PAD + NH + (tid & 1)] = 0.0f;
    }
    __syncthreads();

    if (tid < TSAMP) {
        const int t = tid;
        float acc[NO];
#pragma unroll
        for (int o = 0; o < NO; o++) acc[o] = 0.0f;

        const float* s1n = g_s1 + (size_t)n * NH * TSAMP + t;
#pragma unroll 2
        for (int h = 0; h < NH; h += 2) {
            float sa = s1n[(size_t)h * TSAMP];
            float sb = s1n[(size_t)(h + 1) * TSAMP];
#pragma unroll
            for (int o = 0; o < NO; o++) {
                acc[o] += sa * W2s[o * W2PAD + h];
                acc[o] += sb * W2s[o * W2PAD + h + 1];
            }
        }
#pragma unroll
        for (int o = 0; o < NO; o++) a2s[o][t] = acc[o];
    }
    __syncthreads();

    if (tid < TSAMP) {
        const int t = tid;
        const int kmax = min(KLEN - 1, t);
#pragma unroll 1
        for (int o = 0; o < NO; o++) {
            float u = 0.0f;
            for (int k = 0; k <= kmax; k++)
                u += eps_s[k] * a2s[o][t - k];
            out[((size_t)n * NO + o) * TSAMP + t] = (u >= THETA) ? 1.0f : 0.0f;
        }
    }
}

// ---------------------------------------------------------------------------
extern "C" void kernel_launch(void* const* d_in, const int* in_sizes, int n_in,
                              void* d_out, int out_size)
{
    (void)in_sizes; (void)n_in; (void)out_size;
    const float* img = (const float*)d_in[0];   // [128, 784]
    const float* ru  = (const float*)d_in[1];   // [128, 784, 300]
    const float* W1  = (const float*)d_in[2];   // [410, 784]
    const float* W2  = (const float*)d_in[3];   // [10, 410]
    float* out = (float*)d_out;                 // [128, 10, 300]

    dim3 g1((TSAMP + TTILE - 1) / TTILE,   // 5 t-tiles
            (NH + OT - 1) / OT,            // 7 o-tiles
            NB);                           // 128 batches
    gemm1_kernel<<<g1, 256>>>(img, ru, W1);

    fir1_kernel<<<(NB * NH) / 8, 256>>>();

    fc2_kernel<<<NB, 320>>>(W2, out);
}

// round 6
// speedup vs baseline: 2.6808x; 2.6808x over previous
#include <cuda_runtime.h>
#include <cuda_fp16.h>
#include <math.h>
#include <stdint.h>

// ---------------------------------------------------------------------------
// Problem constants
// ---------------------------------------------------------------------------
#define NB    128
#define NI    784
#define NH    410
#define NO    10
#define TSMP  300
#define KLEN  64
#define THETA 10.0f

#define NHP   416               // a1t column stride (NH padded to 416)
#define NHP2  512               // GEMM N padded to 4 x 128 CTA tiles
#define KP    832               // NI padded to 13*64
#define KC    64                // K per chunk
#define NKC   13
#define MT    128               // M rows per CTA
#define GROWS (NB * TSMP)       // 38400
#define MTILES (GROWS / MT)     // 300 exact

// ---------------------------------------------------------------------------
// Device scratch (no allocation allowed)
// ---------------------------------------------------------------------------
__device__ __half g_s0[(size_t)GROWS * KP];        // encoded spikes fp16 (61MB)
__device__ __half g_whi[(size_t)NHP2 * KP];        // W1 fp16 high part
__device__ __half g_wlo[(size_t)NHP2 * KP];        // W1 fp16 low part
__device__ float  g_a1t[(size_t)GROWS * NHP];      // a1 in [g][o] layout (~64MB)
__device__ float  g_s1[(size_t)NB * NH * TSMP];    // hidden spikes [n][h][t]

// ---------------------------------------------------------------------------
// Helpers
// ---------------------------------------------------------------------------
__device__ __forceinline__ uint32_t smem_u32(const void* p) {
    uint32_t a;
    asm("{ .reg .u64 t; cvta.to.shared.u64 t, %1; cvt.u32.u64 %0, t; }"
        : "=r"(a) : "l"(p));
    return a;
}

__device__ __forceinline__ uint32_t sw128(uint32_t byte) {
    return byte ^ ((byte >> 3) & 0x70u);
}

__device__ __forceinline__ void cp_async16(uint32_t dst, const void* src) {
    asm volatile("cp.async.cg.shared.global [%0], [%1], 16;"
                 :: "r"(dst), "l"(src) : "memory");
}
__device__ __forceinline__ void cp_commit() {
    asm volatile("cp.async.commit_group;" ::: "memory");
}

#define LDSM_X4(r0, r1, r2, r3, addr) \
    asm volatile("ldmatrix.sync.aligned.m8n8.x4.shared.b16 {%0,%1,%2,%3}, [%4];" \
                 : "=r"(r0), "=r"(r1), "=r"(r2), "=r"(r3) : "r"(addr))

#define MMA16816(c, a, b0, b1) \
    asm volatile("mma.sync.aligned.m16n8k16.row.col.f32.f16.f16.f32 " \
                 "{%0,%1,%2,%3}, {%4,%5,%6,%7}, {%8,%9}, {%0,%1,%2,%3};" \
                 : "+f"((c)[0]), "+f"((c)[1]), "+f"((c)[2]), "+f"((c)[3]) \
                 : "r"((a)[0]), "r"((a)[1]), "r"((a)[2]), "r"((a)[3]), \
                   "r"(b0), "r"(b1))

// ---------------------------------------------------------------------------
// Kernel A: split W1 fp32 -> fp16 hi/lo, padded row-major [512][832]
// ---------------------------------------------------------------------------
__global__ __launch_bounds__(256) void split_w_kernel(const float* __restrict__ W1) {
    int idx = blockIdx.x * 256 + threadIdx.x;
    if (idx >= NHP2 * KP) return;
    int o = idx / KP;
    int k = idx - o * KP;
    float w = (o < NH && k < NI) ? W1[o * NI + k] : 0.0f;
    __half hi = __float2half_rn(w);
    __half lo = __float2half_rn(w - __half2float(hi));
    g_whi[idx] = hi;
    g_wlo[idx] = lo;
}

// ---------------------------------------------------------------------------
// Kernel B: Poisson encode -> g_s0[g][i] fp16, g = n*300 + t.
// Block handles 32 g-rows x all i. Coalesced reads + smem transpose.
// ---------------------------------------------------------------------------
__global__ __launch_bounds__(256) void encode_kernel(
    const float* __restrict__ img, const float* __restrict__ ru) {
    __shared__ float sm[64][33];

    const int tid = threadIdx.x;
    const int w = tid >> 5, lane = tid & 31;
    const int g0 = blockIdx.x * 32;

    // this lane's (n, t) for phase A
    const int gA = g0 + lane;
    const int nA = gA / TSMP;
    const int tA = gA - nA * TSMP;
    const float* runA = ru + (size_t)nA * NI * TSMP;
    const float* imnA = img + nA * NI;

    for (int ic = 0; ic < NKC; ic++) {
        // Phase A: read [64 i][32 g] coalesced along t
#pragma unroll
        for (int r = 0; r < 8; r++) {
            int i = ic * 64 + w * 8 + r;
            float v = 0.0f;
            if (i < NI) {
                float rv = __ldg(&runA[(size_t)i * TSMP + tA]);
                float im = __ldg(&imnA[i]);
                v = (rv < im) ? 1.0f : 0.0f;
            }
            sm[w * 8 + r][lane] = v;
        }
        __syncthreads();

        // Phase B: write 32 g-rows x 64 i (128B per row) coalesced
#pragma unroll
        for (int q = 0; q < 4; q++) {
            int gr = w * 4 + q;
            float lo = sm[2 * lane][gr];
            float hi = sm[2 * lane + 1][gr];
            __half2 h2 = __floats2half2_rn(lo, hi);
            *(__half2*)(g_s0 + (size_t)(g0 + gr) * KP + ic * 64 + 2 * lane) = h2;
        }
        __syncthreads();
    }
}

// ---------------------------------------------------------------------------
// Kernel C: HMMA GEMM  D[g][o] = sum_k s0[g][k] * (Whi[o][k] + Wlo[o][k])
// CTA tile 128x128, 8 warps (2x4) of 64x32, K-chunks of 64 double-buffered.
// ---------------------------------------------------------------------------
#define SA(buf)  ((buf) * 16384u)
#define SBH(buf) (32768u + (buf) * 16384u)
#define SBL(buf) (65536u + (buf) * 16384u)
#define SM_GEMM  98304

__global__ __launch_bounds__(256, 2) void gemm1_mma_kernel() {
    extern __shared__ char smem[];
    const uint32_t sb = smem_u32(smem);

    const int tid  = threadIdx.x;
    const int lane = tid & 31;
    const int warp = tid >> 5;
    const int wm   = warp >> 2;       // 0..1  (M 64-half)
    const int wn   = warp & 3;        // 0..3  (N 32-quarter)
    const int mt   = blockIdx.x;      // 0..299
    const int nt   = blockIdx.y;      // 0..3

    // -------- load helper: one K-chunk (A + Bhi + Blo) into buffer --------
    const int lrow = tid >> 3;        // 0..31 base row (x4 iters -> 128 rows? no:)
    const int lj   = tid & 7;         // 16B segment within 128B row
    // seg = tid + it*256 -> row = seg>>3 covers 0..127 over 4 its

    auto issue_chunk = [&](int kc, int buf) {
        const __half* srcA = g_s0 + (size_t)(mt * MT) * KP + kc * KC;
        const __half* srcH = g_whi + (size_t)(nt * 128) * KP + kc * KC;
        const __half* srcL = g_wlo + (size_t)(nt * 128) * KP + kc * KC;
#pragma unroll
        for (int it = 0; it < 4; it++) {
            int row = lrow + it * 32;
            uint32_t off = sw128((uint32_t)row * 128 + lj * 16);
            cp_async16(sb + SA(buf) + off,  srcA + (size_t)row * KP + lj * 8);
            cp_async16(sb + SBH(buf) + off, srcH + (size_t)row * KP + lj * 8);
            cp_async16(sb + SBL(buf) + off, srcL + (size_t)row * KP + lj * 8);
        }
        cp_commit();
    };

    // -------- per-lane ldmatrix base offsets (unswizzled bytes) --------
    const int lt = lane >> 3;         // tile index 0..3
    const int lr = lane & 7;          // row within 8
    // A m16k16 tiles: row_off = (t&1)*8 + lr ; col_off(k) = (t>>1)*8
    const uint32_t a_row = (uint32_t)(wm * 64 + (lt & 1) * 8 + lr);
    const uint32_t a_col = (uint32_t)((lt >> 1) * 8);
    // B x4 (two n8k16 frags): n_off = (t>>1)*8 + lr ; col_off = (t&1)*8
    const uint32_t b_row = (uint32_t)(wn * 32 + (lt >> 1) * 8 + lr);
    const uint32_t b_col = (uint32_t)((lt & 1) * 8);

    float acc[4][4][4];
#pragma unroll
    for (int i = 0; i < 4; i++)
#pragma unroll
        for (int j = 0; j < 4; j++)
#pragma unroll
            for (int q = 0; q < 4; q++) acc[i][j][q] = 0.0f;

    issue_chunk(0, 0);

    for (int kc = 0; kc < NKC; kc++) {
        if (kc + 1 < NKC) issue_chunk(kc + 1, (kc + 1) & 1);
        if (kc + 1 < NKC) {
            asm volatile("cp.async.wait_group 1;" ::: "memory");
        } else {
            asm volatile("cp.async.wait_group 0;" ::: "memory");
        }
        __syncthreads();

        const int buf = kc & 1;
        const uint32_t abase = sb + SA(buf);
        const uint32_t hbase = sb + SBH(buf);
        const uint32_t lbase = sb + SBL(buf);

#pragma unroll
        for (int ks = 0; ks < 4; ks++) {
            uint32_t a[4][4];
#pragma unroll
            for (int mi = 0; mi < 4; mi++) {
                uint32_t byte = (a_row + mi * 16) * 128 + (ks * 16 + a_col) * 2;
                LDSM_X4(a[mi][0], a[mi][1], a[mi][2], a[mi][3], abase + sw128(byte));
            }
            uint32_t bh[2][4], bl[2][4];
#pragma unroll
            for (int nj = 0; nj < 2; nj++) {
                uint32_t byte = (b_row + nj * 16) * 128 + (ks * 16 + b_col) * 2;
                uint32_t swo = sw128(byte);
                LDSM_X4(bh[nj][0], bh[nj][1], bh[nj][2], bh[nj][3], hbase + swo);
                LDSM_X4(bl[nj][0], bl[nj][1], bl[nj][2], bl[nj][3], lbase + swo);
            }
#pragma unroll
            for (int mi = 0; mi < 4; mi++) {
#pragma unroll
                for (int nj = 0; nj < 2; nj++) {
                    MMA16816(acc[mi][nj * 2],     a[mi], bh[nj][0], bh[nj][1]);
                    MMA16816(acc[mi][nj * 2],     a[mi], bl[nj][0], bl[nj][1]);
                    MMA16816(acc[mi][nj * 2 + 1], a[mi], bh[nj][2], bh[nj][3]);
                    MMA16816(acc[mi][nj * 2 + 1], a[mi], bl[nj][2], bl[nj][3]);
                }
            }
        }
        __syncthreads();
    }

    // -------- epilogue: write D rows to g_a1t (stride NHP=416) --------
    const int row_b = mt * MT + wm * 64 + (lane >> 2);
    const int col_b = nt * 128 + wn * 32 + 2 * (lane & 3);
#pragma unroll
    for (int mi = 0; mi < 4; mi++) {
#pragma unroll
        for (int ni = 0; ni < 4; ni++) {
            int c = col_b + ni * 8;
            if (c < NHP) {
                int r = row_b + mi * 16;
                float2 v0 = make_float2(acc[mi][ni][0], acc[mi][ni][1]);
                float2 v1 = make_float2(acc[mi][ni][2], acc[mi][ni][3]);
                *(float2*)&g_a1t[(size_t)r * NHP + c] = v0;
                *(float2*)&g_a1t[(size_t)(r + 8) * NHP + c] = v1;
            }
        }
    }
}

// ---------------------------------------------------------------------------
// Kernel D: PSP FIR (K=64) + threshold on hidden layer.
// Reads a1t[g=n*300+t][o]; writes s1[n][o][t].
// ---------------------------------------------------------------------------
__global__ __launch_bounds__(256) void fir1_kernel() {
    __shared__ float rows[32][304];
    __shared__ float eps_s[KLEN];

    const int tid = threadIdx.x;
    if (tid < KLEN) {
        float tv = (float)tid;
        eps_s[tid] = (tv / 10.0f) * expf(1.0f - tv / 10.0f);
    }
    const int n = blockIdx.y;
    const int o0 = blockIdx.x * 32;

    {
        const int j = tid & 7, tr = tid >> 3;
#pragma unroll
        for (int p = 0; p < 10; p++) {
            int t = p * 32 + tr;
            if (t < TSMP) {
                float4 v = *(const float4*)&g_a1t[((size_t)n * TSMP + t) * NHP + o0 + j * 4];
                rows[j * 4 + 0][t] = v.x;
                rows[j * 4 + 1][t] = v.y;
                rows[j * 4 + 2][t] = v.z;
                rows[j * 4 + 3][t] = v.w;
            }
        }
    }
    __syncthreads();

    const int w = tid >> 5, lane = tid & 31;
    if (lane < 30) {
        const int t0 = lane * 10;
#pragma unroll 1
        for (int oi = 0; oi < 4; oi++) {
            const int ol = w * 4 + oi;
            float acc[10];
#pragma unroll
            for (int j = 0; j < 10; j++) acc[j] = 0.0f;

#pragma unroll
            for (int kb = 0; kb < KLEN; kb += 16) {
                float ev[16];
#pragma unroll
                for (int q = 0; q < 16; q++) ev[q] = eps_s[kb + q];
                float rv[25];
#pragma unroll
                for (int r = 0; r < 25; r++) {
                    int idx = t0 + 9 - kb - r;
                    rv[r] = (idx >= 0) ? rows[ol][idx] : 0.0f;
                }
#pragma unroll
                for (int j = 0; j < 10; j++)
#pragma unroll
                    for (int q = 0; q < 16; q++)
                        acc[j] += ev[q] * rv[(9 - j) + q];
            }
            const int og = o0 + ol;
            if (og < NH) {
#pragma unroll
                for (int j = 0; j < 10; j++)
                    g_s1[((size_t)n * NH + og) * TSMP + t0 + j] =
                        (acc[j] >= THETA) ? 1.0f : 0.0f;
            }
        }
    }
}

// ---------------------------------------------------------------------------
// Kernel E: fused fc2 GEMM + PSP FIR + threshold. Grid (2 t-blocks, n).
// ---------------------------------------------------------------------------
#define W2PAD 412

__global__ __launch_bounds__(256) void fc2_kernel(const float* __restrict__ W2,
                                                  float* __restrict__ out) {
    __shared__ float W2s[NO * W2PAD];
    __shared__ float a2s[NO][216];
    __shared__ float eps_s[KLEN];

    const int tid = threadIdx.x;
    const int n = blockIdx.y;
    const int tb = blockIdx.x;

    if (tid < KLEN) {
        float tv = (float)tid;
        eps_s[tid] = (tv / 10.0f) * expf(1.0f - tv / 10.0f);
    }
    for (int i = tid; i < NO * NH; i += 256) {
        int o = i / NH, h = i - o * NH;
        W2s[o * W2PAD + h] = W2[i];
    }
    if (tid < NO * 2) {
        int o = tid >> 1;
        W2s[o * W2PAD + NH + (tid & 1)] = 0.0f;
    }
    __syncthreads();

    const int ts = tb * 150;
    const int tstart = (ts >= 63) ? (ts - 63) : 0;
    const int count = ts + 150 - tstart;

    if (tid < count) {
        const int t = tstart + tid;
        float acc[NO];
#pragma unroll
        for (int o = 0; o < NO; o++) acc[o] = 0.0f;
        const float* s1n = g_s1 + (size_t)n * NH * TSMP + t;
#pragma unroll 2
        for (int h = 0; h < NH; h += 2) {
            float sa = s1n[(size_t)h * TSMP];
            float sb2 = s1n[(size_t)(h + 1) * TSMP];
#pragma unroll
            for (int o = 0; o < NO; o++) {
                acc[o] += sa * W2s[o * W2PAD + h];
                acc[o] += sb2 * W2s[o * W2PAD + h + 1];
            }
        }
#pragma unroll
        for (int o = 0; o < NO; o++) a2s[o][tid] = acc[o];
    }
    __syncthreads();

    if (tid < 150) {
        const int t = ts + tid;
        const int L = t - tstart;
        const int kmax = min(KLEN - 1, t);
#pragma unroll 1
        for (int o = 0; o < NO; o++) {
            float u = 0.0f;
            for (int k = 0; k <= kmax; k++)
                u += eps_s[k] * a2s[o][L - k];
            out[((size_t)n * NO + o) * TSMP + t] = (u >= THETA) ? 1.0f : 0.0f;
        }
    }
}

// ---------------------------------------------------------------------------
extern "C" void kernel_launch(void* const* d_in, const int* in_sizes, int n_in,
                              void* d_out, int out_size) {
    (void)in_sizes; (void)n_in; (void)out_size;
    const float* img = (const float*)d_in[0];   // [128, 784]
    const float* ru  = (const float*)d_in[1];   // [128, 784, 300]
    const float* W1  = (const float*)d_in[2];   // [410, 784]
    const float* W2  = (const float*)d_in[3];   // [10, 410]
    float* out = (float*)d_out;                 // [128, 10, 300]

    split_w_kernel<<<(NHP2 * KP + 255) / 256, 256>>>(W1);
    encode_kernel<<<GROWS / 32, 256>>>(img, ru);

    static int smem_set = 0;
    if (!smem_set) {
        cudaFuncSetAttribute(gemm1_mma_kernel,
                             cudaFuncAttributeMaxDynamicSharedMemorySize, SM_GEMM);
        smem_set = 1;
    }
    gemm1_mma_kernel<<<dim3(MTILES, 4), 256, SM_GEMM>>>();

    fir1_kernel<<<dim3(13, NB), 256>>>();

    fc2_kernel<<<dim3(2, NB), 256>>>(W2, out);
}

// round 7
// speedup vs baseline: 2.9728x; 1.1089x over previous
#include <cuda_runtime.h>
#include <cuda_fp16.h>
#include <math.h>
#include <stdint.h>

// ---------------------------------------------------------------------------
// Problem constants
// ---------------------------------------------------------------------------
#define NB    128
#define NI    784
#define NH    410
#define NO    10
#define TSMP  300
#define KLEN  64
#define THETA 10.0f

#define NHP   416               // a1t column stride (NH padded to 416)
#define NHP2  512               // GEMM N padded to 4 x 128 CTA tiles
#define KP    832               // NI padded to 13*64
#define KC    64                // K per chunk
#define NKC   13
#define MT    128               // M rows per CTA
#define GROWS (NB * TSMP)       // 38400
#define MTILES (GROWS / MT)     // 300 exact

// SRM alpha-kernel taps eps[k] = (k/10)*exp(1-k/10) as compile-time float
// literals -> ptxas emits immediate-form FFMA (rt 1 vs 2 = 2x fp32 rate).
__device__ constexpr float EPS[KLEN] = {
    0.0000000000f, 0.2459603111f, 0.4451081857f, 0.6041258122f,
    0.7288475202f, 0.8243606354f, 0.8950948186f, 0.9449011654f,
    0.9771222064f, 0.9946538264f, 1.0000000000f, 0.9953211600f,
    0.9824769037f, 0.9630636870f, 0.9384480644f, 0.9097959895f,
    0.8780986178f, 0.8441950164f, 0.8087921356f, 0.7724823532f,
    0.7357588823f, 0.6990292760f, 0.6626272664f, 0.6268231239f,
    0.5918327133f, 0.5578254003f, 0.5249309464f, 0.4932455146f,
    0.4628368866f, 0.4337489957f, 0.4060058497f, 0.3796149272f,
    0.3545701066f, 0.3308541851f, 0.3084410408f, 0.2872974963f,
    0.2673848822f, 0.2486603977f, 0.2310782389f, 0.2145905593f,
    0.1991482735f, 0.1847017280f, 0.1712012558f, 0.1585976196f,
    0.1468423867f, 0.1358882254f, 0.1256891229f, 0.1162005724f,
    0.1073797042f, 0.0991853624f, 0.0915781944f, 0.0845206424f,
    0.0779770014f, 0.0719133646f, 0.0662976344f, 0.0610994814f,
    0.0562902814f, 0.0518430787f, 0.0477325337f, 0.0439348398f,
    0.0404276820f, 0.0371901540f, 0.0342026963f, 0.0314470440f
};

// ---------------------------------------------------------------------------
// Device scratch (no allocation allowed)
// ---------------------------------------------------------------------------
__device__ __half g_s0[(size_t)GROWS * KP];        // encoded spikes fp16 (61MB)
__device__ __half g_whi[(size_t)NHP2 * KP];        // W1 fp16 high part
__device__ __half g_wlo[(size_t)NHP2 * KP];        // W1 fp16 low part
__device__ float  g_a1t[(size_t)GROWS * NHP];      // a1 in [g][o] layout (~64MB)
__device__ float  g_s1[(size_t)NB * NH * TSMP];    // hidden spikes [n][h][t]

// ---------------------------------------------------------------------------
// Helpers
// ---------------------------------------------------------------------------
__device__ __forceinline__ uint32_t smem_u32(const void* p) {
    uint32_t a;
    asm("{ .reg .u64 t; cvta.to.shared.u64 t, %1; cvt.u32.u64 %0, t; }"
        : "=r"(a) : "l"(p));
    return a;
}

__device__ __forceinline__ uint32_t sw128(uint32_t byte) {
    return byte ^ ((byte >> 3) & 0x70u);
}

__device__ __forceinline__ void cp_async16(uint32_t dst, const void* src) {
    asm volatile("cp.async.cg.shared.global [%0], [%1], 16;"
                 :: "r"(dst), "l"(src) : "memory");
}
__device__ __forceinline__ void cp_commit() {
    asm volatile("cp.async.commit_group;" ::: "memory");
}

#define LDSM_X4(r0, r1, r2, r3, addr) \
    asm volatile("ldmatrix.sync.aligned.m8n8.x4.shared.b16 {%0,%1,%2,%3}, [%4];" \
                 : "=r"(r0), "=r"(r1), "=r"(r2), "=r"(r3) : "r"(addr))

#define MMA16816(c, a, b0, b1) \
    asm volatile("mma.sync.aligned.m16n8k16.row.col.f32.f16.f16.f32 " \
                 "{%0,%1,%2,%3}, {%4,%5,%6,%7}, {%8,%9}, {%0,%1,%2,%3};" \
                 : "+f"((c)[0]), "+f"((c)[1]), "+f"((c)[2]), "+f"((c)[3]) \
                 : "r"((a)[0]), "r"((a)[1]), "r"((a)[2]), "r"((a)[3]), \
                   "r"(b0), "r"(b1))

// ---------------------------------------------------------------------------
// Kernel A: split W1 fp32 -> fp16 hi/lo, padded row-major [512][832]
// ---------------------------------------------------------------------------
__global__ __launch_bounds__(256) void split_w_kernel(const float* __restrict__ W1) {
    int idx = blockIdx.x * 256 + threadIdx.x;
    if (idx >= NHP2 * KP) return;
    int o = idx / KP;
    int k = idx - o * KP;
    float w = (o < NH && k < NI) ? W1[o * NI + k] : 0.0f;
    __half hi = __float2half_rn(w);
    __half lo = __float2half_rn(w - __half2float(hi));
    g_whi[idx] = hi;
    g_wlo[idx] = lo;
}

// ---------------------------------------------------------------------------
// Kernel B: Poisson encode -> g_s0[g][i] fp16, g = n*300 + t.
// ---------------------------------------------------------------------------
__global__ __launch_bounds__(256) void encode_kernel(
    const float* __restrict__ img, const float* __restrict__ ru) {
    __shared__ float sm[64][33];

    const int tid = threadIdx.x;
    const int w = tid >> 5, lane = tid & 31;
    const int g0 = blockIdx.x * 32;

    const int gA = g0 + lane;
    const int nA = gA / TSMP;
    const int tA = gA - nA * TSMP;
    const float* runA = ru + (size_t)nA * NI * TSMP;
    const float* imnA = img + nA * NI;

    for (int ic = 0; ic < NKC; ic++) {
#pragma unroll
        for (int r = 0; r < 8; r++) {
            int i = ic * 64 + w * 8 + r;
            float v = 0.0f;
            if (i < NI) {
                float rv = __ldg(&runA[(size_t)i * TSMP + tA]);
                float im = __ldg(&imnA[i]);
                v = (rv < im) ? 1.0f : 0.0f;
            }
            sm[w * 8 + r][lane] = v;
        }
        __syncthreads();

#pragma unroll
        for (int q = 0; q < 4; q++) {
            int gr = w * 4 + q;
            float lo = sm[2 * lane][gr];
            float hi = sm[2 * lane + 1][gr];
            __half2 h2 = __floats2half2_rn(lo, hi);
            *(__half2*)(g_s0 + (size_t)(g0 + gr) * KP + ic * 64 + 2 * lane) = h2;
        }
        __syncthreads();
    }
}

// ---------------------------------------------------------------------------
// Kernel C: HMMA GEMM  D[g][o] = sum_k s0[g][k] * (Whi[o][k] + Wlo[o][k])
// Grid (nt=4, mt=300): nt fastest so the 4 column-blocks of one mt are
// wave-adjacent -> A tile read from DRAM once, reused via L2.
// ---------------------------------------------------------------------------
#define SA(buf)  ((buf) * 16384u)
#define SBH(buf) (32768u + (buf) * 16384u)
#define SBL(buf) (65536u + (buf) * 16384u)
#define SM_GEMM  98304

__global__ __launch_bounds__(256, 2) void gemm1_mma_kernel() {
    extern __shared__ char smem[];
    const uint32_t sb = smem_u32(smem);

    const int tid  = threadIdx.x;
    const int lane = tid & 31;
    const int warp = tid >> 5;
    const int wm   = warp >> 2;       // 0..1  (M 64-half)
    const int wn   = warp & 3;        // 0..3  (N 32-quarter)
    const int nt   = blockIdx.x;      // 0..3
    const int mt   = blockIdx.y;      // 0..299

    const int lrow = tid >> 3;
    const int lj   = tid & 7;

    auto issue_chunk = [&](int kc, int buf) {
        const __half* srcA = g_s0 + (size_t)(mt * MT) * KP + kc * KC;
        const __half* srcH = g_whi + (size_t)(nt * 128) * KP + kc * KC;
        const __half* srcL = g_wlo + (size_t)(nt * 128) * KP + kc * KC;
#pragma unroll
        for (int it = 0; it < 4; it++) {
            int row = lrow + it * 32;
            uint32_t off = sw128((uint32_t)row * 128 + lj * 16);
            cp_async16(sb + SA(buf) + off,  srcA + (size_t)row * KP + lj * 8);
            cp_async16(sb + SBH(buf) + off, srcH + (size_t)row * KP + lj * 8);
            cp_async16(sb + SBL(buf) + off, srcL + (size_t)row * KP + lj * 8);
        }
        cp_commit();
    };

    const int lt = lane >> 3;
    const int lr = lane & 7;
    const uint32_t a_row = (uint32_t)(wm * 64 + (lt & 1) * 8 + lr);
    const uint32_t a_col = (uint32_t)((lt >> 1) * 8);
    const uint32_t b_row = (uint32_t)(wn * 32 + (lt >> 1) * 8 + lr);
    const uint32_t b_col = (uint32_t)((lt & 1) * 8);

    float acc[4][4][4];
#pragma unroll
    for (int i = 0; i < 4; i++)
#pragma unroll
        for (int j = 0; j < 4; j++)
#pragma unroll
            for (int q = 0; q < 4; q++) acc[i][j][q] = 0.0f;

    issue_chunk(0, 0);

    for (int kc = 0; kc < NKC; kc++) {
        if (kc + 1 < NKC) issue_chunk(kc + 1, (kc + 1) & 1);
        if (kc + 1 < NKC) {
            asm volatile("cp.async.wait_group 1;" ::: "memory");
        } else {
            asm volatile("cp.async.wait_group 0;" ::: "memory");
        }
        __syncthreads();

        const int buf = kc & 1;
        const uint32_t abase = sb + SA(buf);
        const uint32_t hbase = sb + SBH(buf);
        const uint32_t lbase = sb + SBL(buf);

#pragma unroll
        for (int ks = 0; ks < 4; ks++) {
            uint32_t a[4][4];
#pragma unroll
            for (int mi = 0; mi < 4; mi++) {
                uint32_t byte = (a_row + mi * 16) * 128 + (ks * 16 + a_col) * 2;
                LDSM_X4(a[mi][0], a[mi][1], a[mi][2], a[mi][3], abase + sw128(byte));
            }
            uint32_t bh[2][4], bl[2][4];
#pragma unroll
            for (int nj = 0; nj < 2; nj++) {
                uint32_t byte = (b_row + nj * 16) * 128 + (ks * 16 + b_col) * 2;
                uint32_t swo = sw128(byte);
                LDSM_X4(bh[nj][0], bh[nj][1], bh[nj][2], bh[nj][3], hbase + swo);
                LDSM_X4(bl[nj][0], bl[nj][1], bl[nj][2], bl[nj][3], lbase + swo);
            }
#pragma unroll
            for (int mi = 0; mi < 4; mi++) {
#pragma unroll
                for (int nj = 0; nj < 2; nj++) {
                    MMA16816(acc[mi][nj * 2],     a[mi], bh[nj][0], bh[nj][1]);
                    MMA16816(acc[mi][nj * 2],     a[mi], bl[nj][0], bl[nj][1]);
                    MMA16816(acc[mi][nj * 2 + 1], a[mi], bh[nj][2], bh[nj][3]);
                    MMA16816(acc[mi][nj * 2 + 1], a[mi], bl[nj][2], bl[nj][3]);
                }
            }
        }
        __syncthreads();
    }

    const int row_b = mt * MT + wm * 64 + (lane >> 2);
    const int col_b = nt * 128 + wn * 32 + 2 * (lane & 3);
#pragma unroll
    for (int mi = 0; mi < 4; mi++) {
#pragma unroll
        for (int ni = 0; ni < 4; ni++) {
            int c = col_b + ni * 8;
            if (c < NHP) {
                int r = row_b + mi * 16;
                float2 v0 = make_float2(acc[mi][ni][0], acc[mi][ni][1]);
                float2 v1 = make_float2(acc[mi][ni][2], acc[mi][ni][3]);
                *(float2*)&g_a1t[(size_t)r * NHP + c] = v0;
                *(float2*)&g_a1t[(size_t)(r + 8) * NHP + c] = v1;
            }
        }
    }
}

// ---------------------------------------------------------------------------
// Kernel D: PSP FIR (K=64, immediate taps) + threshold on hidden layer.
// ---------------------------------------------------------------------------
__global__ __launch_bounds__(256) void fir1_kernel() {
    __shared__ float rows[32][304];

    const int tid = threadIdx.x;
    const int n = blockIdx.y;
    const int o0 = blockIdx.x * 32;

    {
        const int j = tid & 7, tr = tid >> 3;
#pragma unroll
        for (int p = 0; p < 10; p++) {
            int t = p * 32 + tr;
            if (t < TSMP) {
                float4 v = *(const float4*)&g_a1t[((size_t)n * TSMP + t) * NHP + o0 + j * 4];
                rows[j * 4 + 0][t] = v.x;
                rows[j * 4 + 1][t] = v.y;
                rows[j * 4 + 2][t] = v.z;
                rows[j * 4 + 3][t] = v.w;
            }
        }
    }
    __syncthreads();

    const int w = tid >> 5, lane = tid & 31;
    if (lane < 30) {
        const int t0 = lane * 10;
#pragma unroll 1
        for (int oi = 0; oi < 4; oi++) {
            const int ol = w * 4 + oi;
            float acc[10];
#pragma unroll
            for (int j = 0; j < 10; j++) acc[j] = 0.0f;

#pragma unroll
            for (int kb = 0; kb < KLEN; kb += 16) {
                float rv[25];
#pragma unroll
                for (int r = 0; r < 25; r++) {
                    int idx = t0 + 9 - kb - r;
                    rv[r] = (idx >= 0) ? rows[ol][idx] : 0.0f;
                }
#pragma unroll
                for (int j = 0; j < 10; j++)
#pragma unroll
                    for (int q = 0; q < 16; q++)
                        acc[j] += EPS[kb + q] * rv[(9 - j) + q];   // FFMA-imm
            }
            const int og = o0 + ol;
            if (og < NH) {
#pragma unroll
                for (int j = 0; j < 10; j++)
                    g_s1[((size_t)n * NH + og) * TSMP + t0 + j] =
                        (acc[j] >= THETA) ? 1.0f : 0.0f;
            }
        }
    }
}

// ---------------------------------------------------------------------------
// Kernel E: fused fc2 GEMM + PSP FIR + threshold. Grid (2 t-blocks, n).
// Zero-padded a2 history -> fixed 64-tap FIR with immediate eps.
// ---------------------------------------------------------------------------
#define W2PAD 412
#define OFFH  64

__global__ __launch_bounds__(256) void fc2_kernel(const float* __restrict__ W2,
                                                  float* __restrict__ out) {
    __shared__ float W2s[NO * W2PAD];
    __shared__ float a2s[NO][OFFH + 216];

    const int tid = threadIdx.x;
    const int n = blockIdx.y;
    const int tb = blockIdx.x;

    for (int i = tid; i < NO * NH; i += 256) {
        int o = i / NH, h = i - o * NH;
        W2s[o * W2PAD + h] = W2[i];
    }
    if (tid < NO * 2) {
        int o = tid >> 1;
        W2s[o * W2PAD + NH + (tid & 1)] = 0.0f;
    }
    for (int i = tid; i < NO * OFFH; i += 256) {
        int o = i >> 6;
        a2s[o][i & 63] = 0.0f;
    }
    __syncthreads();

    const int ts = tb * 150;
    const int tstart = (ts >= 63) ? (ts - 63) : 0;
    const int count = ts + 150 - tstart;     // 150 or 213

    if (tid < count) {
        const int t = tstart + tid;
        float acc[NO];
#pragma unroll
        for (int o = 0; o < NO; o++) acc[o] = 0.0f;
        const float* s1n = g_s1 + (size_t)n * NH * TSMP + t;
#pragma unroll 2
        for (int h = 0; h < 408; h += 4) {
            float sa = s1n[(size_t)h * TSMP];
            float sb = s1n[(size_t)(h + 1) * TSMP];
            float sc = s1n[(size_t)(h + 2) * TSMP];
            float sd = s1n[(size_t)(h + 3) * TSMP];
#pragma unroll
            for (int o = 0; o < NO; o++) {
                float4 w = *(const float4*)&W2s[o * W2PAD + h];
                acc[o] += sa * w.x + sb * w.y + sc * w.z + sd * w.w;
            }
        }
        {
            float sa = s1n[(size_t)408 * TSMP];
            float sb = s1n[(size_t)409 * TSMP];
#pragma unroll
            for (int o = 0; o < NO; o++)
                acc[o] += sa * W2s[o * W2PAD + 408] + sb * W2s[o * W2PAD + 409];
        }
#pragma unroll
        for (int o = 0; o < NO; o++) a2s[o][OFFH + tid] = acc[o];
    }
    __syncthreads();

    if (tid < 150) {
        const int t = ts + tid;
        const int L = OFFH + (t - tstart);
#pragma unroll 1
        for (int o = 0; o < NO; o++) {
            float u = 0.0f;
#pragma unroll
            for (int k = 0; k < KLEN; k++)
                u += EPS[k] * a2s[o][L - k];     // FFMA-imm; pad zeros cover t<63
            out[((size_t)n * NO + o) * TSMP + t] = (u >= THETA) ? 1.0f : 0.0f;
        }
    }
}

// ---------------------------------------------------------------------------
extern "C" void kernel_launch(void* const* d_in, const int* in_sizes, int n_in,
                              void* d_out, int out_size) {
    (void)in_sizes; (void)n_in; (void)out_size;
    const float* img = (const float*)d_in[0];   // [128, 784]
    const float* ru  = (const float*)d_in[1];   // [128, 784, 300]
    const float* W1  = (const float*)d_in[2];   // [410, 784]
    const float* W2  = (const float*)d_in[3];   // [10, 410]
    float* out = (float*)d_out;                 // [128, 10, 300]

    split_w_kernel<<<(NHP2 * KP + 255) / 256, 256>>>(W1);
    encode_kernel<<<GROWS / 32, 256>>>(img, ru);

    cudaFuncSetAttribute(gemm1_mma_kernel,
                         cudaFuncAttributeMaxDynamicSharedMemorySize, SM_GEMM);
    gemm1_mma_kernel<<<dim3(4, MTILES), 256, SM_GEMM>>>();

    fir1_kernel<<<dim3(13, NB), 256>>>();

    fc2_kernel<<<dim3(2, NB), 256>>>(W2, out);
}